// round 8
// baseline (speedup 1.0000x reference)
#include <cuda_runtime.h>
#include <cuda_bf16.h>
#include <cstdint>

#define NUM_TAGS 9
#define DDIM 64
#define HID 768
#define SEQ 512
#define BATCH 16
#define NQK (NUM_TAGS * 2 * DDIM)   /* 1152 */
#define MASKV 1e12f

// Scratch
__device__ __nv_bfloat16 g_Q[(size_t)BATCH * NUM_TAGS * SEQ * DDIM];
__device__ __nv_bfloat16 g_K[(size_t)BATCH * NUM_TAGS * SEQ * DDIM];
__device__ __nv_bfloat16 g_encb[(size_t)BATCH * SEQ * HID];      // enc in bf16
__device__ __nv_bfloat16 g_Wt[(size_t)NQK * HID];                // W^T bf16 [n][k]
__device__ float2 g_rope[SEQ * 32];                              // (sin,cos) per (s,pair)

__device__ __forceinline__ uint32_t smem_u32(const void* p) {
    uint32_t a;
    asm("{ .reg .u64 t; cvta.to.shared.u64 t, %1; cvt.u32.u64 %0, t; }" : "=r"(a) : "l"(p));
    return a;
}
__device__ __forceinline__ void cpasync16s(uint32_t saddr, const void* g) {
    asm volatile("cp.async.cg.shared.global [%0], [%1], 16;\n" :: "r"(saddr), "l"(g));
}
#define CP_COMMIT() asm volatile("cp.async.commit_group;\n")
#define SW128(o) ((o) ^ (((o) >> 3) & 0x70))

__device__ __forceinline__ void mma16816(float* c, const unsigned* a, const unsigned* b) {
    asm volatile(
        "mma.sync.aligned.m16n8k16.row.col.f32.bf16.bf16.f32 "
        "{%0,%1,%2,%3}, {%4,%5,%6,%7}, {%8,%9}, {%0,%1,%2,%3};\n"
        : "+f"(c[0]), "+f"(c[1]), "+f"(c[2]), "+f"(c[3])
        : "r"(a[0]), "r"(a[1]), "r"(a[2]), "r"(a[3]), "r"(b[0]), "r"(b[1]));
}
__device__ __forceinline__ void ldsm_x4(uint32_t addr, uint32_t* r) {
    asm volatile("ldmatrix.sync.aligned.m8n8.x4.shared.b16 {%0,%1,%2,%3}, [%4];"
        : "=r"(r[0]), "=r"(r[1]), "=r"(r[2]), "=r"(r[3]) : "r"(addr));
}
__device__ __forceinline__ void stcs128(float* g, float4 v) {
    asm volatile("st.global.cs.v4.f32 [%0], {%1,%2,%3,%4};"
        :: "l"(g), "f"(v.x), "f"(v.y), "f"(v.z), "f"(v.w) : "memory");
}

// ===================== Prep kernels =====================
__global__ __launch_bounds__(256) void prep_enc(const float* __restrict__ enc,
                                                __nv_bfloat16* __restrict__ dst) {
    const int NV = BATCH * SEQ * HID / 4;
    const int stride = gridDim.x * blockDim.x;
    for (int i = blockIdx.x * blockDim.x + threadIdx.x; i < NV; i += stride) {
        float4 v = *(const float4*)(enc + (size_t)i * 4);
        __nv_bfloat162 lo = __floats2bfloat162_rn(v.x, v.y);
        __nv_bfloat162 hi = __floats2bfloat162_rn(v.z, v.w);
        uint2 o = { *(unsigned*)&lo, *(unsigned*)&hi };
        *(uint2*)(dst + (size_t)i * 4) = o;
    }
}

__global__ __launch_bounds__(256) void prep_w(const float* __restrict__ W,
                                              __nv_bfloat16* __restrict__ Wt) {
    __shared__ __nv_bfloat16 t[64][72];
    const int kb = blockIdx.x * 64, nb = blockIdx.y * 64;
    const int tid = threadIdx.x;
    #pragma unroll
    for (int it = 0; it < 4; ++it) {
        int idx = tid + it * 256;
        int r = idx >> 4, c4 = (idx & 15) * 4;
        float4 v = *(const float4*)(W + (size_t)(kb + r) * NQK + nb + c4);
        t[c4 + 0][r] = __float2bfloat16_rn(v.x);
        t[c4 + 1][r] = __float2bfloat16_rn(v.y);
        t[c4 + 2][r] = __float2bfloat16_rn(v.z);
        t[c4 + 3][r] = __float2bfloat16_rn(v.w);
    }
    __syncthreads();
    #pragma unroll
    for (int it = 0; it < 4; ++it) {
        int idx = tid + it * 256;
        int r = idx >> 4, c4 = (idx & 15) * 4;
        *(uint2*)(Wt + (size_t)(nb + r) * HID + kb + c4) = *(uint2*)&t[r][c4];
    }
}

__global__ __launch_bounds__(256) void prep_rope(float2* __restrict__ rope) {
    int i = blockIdx.x * blockDim.x + threadIdx.x;
    if (i >= SEQ * 32) return;
    int s = i >> 5, p = i & 31;
    const float LN1E4_OVER_32 = 0.28782313662425572f;
    float inv = expf(-(float)p * LN1E4_OVER_32);
    float sv, cv;
    sincosf((float)s * inv, &sv, &cv);
    rope[i] = make_float2(sv, cv);
}

// ===================== Kernel A: GEMM1 + bias + RoPE =====================
// CTA tile 128(M) x 128(N = one tag). 4 warps = 2(M) x 2(N); warp tile 64x64.
// K-tile 64 (SW128), 2-stage cp.async. Maximizes MMA-FLOP per crossbar byte.
#define G1_KT 64
#define G1_ASZ (128 * 128)           /* 16KB */
#define G1_BSZ (128 * 128)           /* 16KB */
#define G1_STAGE (G1_ASZ + G1_BSZ)   /* 32KB */
#define G1_NT (HID / G1_KT)          /* 12 */
#define G1_DYN (2 * G1_STAGE + 256)

__global__ __launch_bounds__(128, 2) void gemm1_rope(const float* __restrict__ bias)
{
    extern __shared__ char dyn_raw[];
    const uint32_t dsm = (smem_u32(dyn_raw) + 127) & ~127u;
    __shared__ float s_bias[128];

    const int tid  = threadIdx.x;
    const int lane = tid & 31, wid = tid >> 5;
    const int warp_m = wid & 1;        // 0..1
    const int warp_n = wid >> 1;       // 0..1 (0 -> Q cols, 1 -> K cols)
    const int g  = lane >> 2;
    const int t4 = lane & 3;

    const int m0 = blockIdx.x * 128;
    const int tag = blockIdx.y;
    const int n0 = tag * 128;

    if (tid < 128) s_bias[tid] = bias[n0 + tid];

    const __nv_bfloat16* Ag = g_encb + (size_t)m0 * HID;
    const __nv_bfloat16* Bg = g_Wt   + (size_t)n0 * HID;

    float acc[4][8][4];
    #pragma unroll
    for (int mi = 0; mi < 4; ++mi)
        #pragma unroll
        for (int ni = 0; ni < 8; ++ni)
            #pragma unroll
            for (int q = 0; q < 4; ++q) acc[mi][ni][q] = 0.f;

    auto load_tile = [&](int kt, int st) {
        const int k0 = kt * G1_KT;
        const uint32_t abase = dsm + st * G1_STAGE;
        const uint32_t bbase = abase + G1_ASZ;
        #pragma unroll
        for (int i = 0; i < 8; ++i) {                  // A: 128 rows x 8 chunks
            int idx = tid + i * 128;
            int r = idx >> 3, c = idx & 7;
            uint32_t off = (uint32_t)(r * 128 + c * 16);
            cpasync16s(abase + SW128(off), Ag + (size_t)r * HID + k0 + c * 8);
        }
        #pragma unroll
        for (int i = 0; i < 8; ++i) {                  // B: 128 rows x 8 chunks
            int idx = tid + i * 128;
            int r = idx >> 3, c = idx & 7;
            uint32_t off = (uint32_t)(r * 128 + c * 16);
            cpasync16s(bbase + SW128(off), Bg + (size_t)r * HID + k0 + c * 8);
        }
    };

    load_tile(0, 0); CP_COMMIT();
    load_tile(1, 1); CP_COMMIT();

    const uint32_t aK = ((lane >> 4) << 3) * 2;
    const uint32_t bK = (((lane >> 3) & 1) << 3) * 2;

    for (int kt = 0; kt < G1_NT; ++kt) {
        const int st = kt & 1;
        if (kt + 1 < G1_NT) asm volatile("cp.async.wait_group 1;\n" ::: "memory");
        else                asm volatile("cp.async.wait_group 0;\n" ::: "memory");
        __syncthreads();

        const uint32_t abase = dsm + st * G1_STAGE;
        const uint32_t bbase = abase + G1_ASZ;

        uint32_t arb[4], axv[4];
        #pragma unroll
        for (int mi = 0; mi < 4; ++mi) {
            int r = warp_m * 64 + mi * 16 + (lane & 15);
            arb[mi] = abase + r * 128;
            axv[mi] = (r & 7) << 4;
        }
        uint32_t brb[4], bxv[4];
        #pragma unroll
        for (int nj = 0; nj < 4; ++nj) {
            int n = warp_n * 64 + nj * 16 + ((lane >> 4) << 3) + (lane & 7);
            brb[nj] = bbase + n * 128;
            bxv[nj] = (n & 7) << 4;
        }

        #pragma unroll
        for (int kk2 = 0; kk2 < 128; kk2 += 32) {      // 4 k-steps of k=16
            uint32_t a[4][4], b[4][4];
            #pragma unroll
            for (int mi = 0; mi < 4; ++mi)
                ldsm_x4(arb[mi] + ((kk2 + aK) ^ axv[mi]), a[mi]);
            #pragma unroll
            for (int nj = 0; nj < 4; ++nj)
                ldsm_x4(brb[nj] + ((kk2 + bK) ^ bxv[nj]), b[nj]);
            #pragma unroll
            for (int mi = 0; mi < 4; ++mi) {
                #pragma unroll
                for (int ni = 0; ni < 8; ++ni)
                    mma16816(acc[mi][ni], a[mi], &b[ni >> 1][(ni & 1) * 2]);
            }
        }
        __syncthreads();
        if (kt + 2 < G1_NT) { load_tile(kt + 2, st); CP_COMMIT(); }
    }

    // ---- Epilogue: bias + RoPE -> bf16 (warp_n=0 writes Q, =1 writes K) ----
    __nv_bfloat16* dstbase = warp_n ? g_K : g_Q;
    #pragma unroll
    for (int ni = 0; ni < 8; ++ni) {
        const int dcol = ni * 8 + t4 * 2;               // 0..63 within Q or K
        const float b0 = s_bias[warp_n * 64 + dcol];
        const float b1 = s_bias[warp_n * 64 + dcol + 1];
        #pragma unroll
        for (int mi = 0; mi < 4; ++mi) {
            #pragma unroll
            for (int rr = 0; rr < 2; ++rr) {
                const int m = m0 + warp_m * 64 + mi * 16 + g + rr * 8;
                const int bb = m >> 9, s = m & 511;
                float2 sc = g_rope[s * 32 + (dcol >> 1)];
                float v0 = acc[mi][ni][rr * 2 + 0] + b0;
                float v1 = acc[mi][ni][rr * 2 + 1] + b1;
                float y0 = v0 * sc.y - v1 * sc.x;
                float y1 = v1 * sc.y + v0 * sc.x;
                size_t off = (((size_t)(bb * NUM_TAGS + tag) * SEQ + s) * DDIM + dcol);
                *(__nv_bfloat162*)(dstbase + off) = __floats2bfloat162_rn(y0, y1);
            }
        }
    }
}

// ===================== Kernel B: QK^T + mask + scale =====================
// 512 threads, 16 warps as 4(m)x4(n), warp tile 32x32, ldmatrix fragments.
// Epilogue staged through smem -> coalesced float4 streaming stores.
__global__ __launch_bounds__(512, 2) void gemm2_mask(
    const int* __restrict__ amask, float* __restrict__ out)
{
    const int tt = blockIdx.x;
    const int st = blockIdx.y;
    const int bh = blockIdx.z;
    const int bidx = bh / NUM_TAGS;
    const int t0 = tt * 128, s0 = st * 128;
    const int tid = threadIdx.x;

    float* outrow0 = out + ((size_t)bh * SEQ + s0) * SEQ;

    if (t0 < s0) {
        #pragma unroll
        for (int it = 0; it < 8; ++it) {
            int idx = tid + it * 512;
            int r = idx >> 5, c4 = (idx & 31) * 4;
            int4 mv = *(const int4*)(amask + bidx * SEQ + t0 + c4);
            float4 o;
            o.x = ((float)mv.x - 2.0f) * 1.25e11f;
            o.y = ((float)mv.y - 2.0f) * 1.25e11f;
            o.z = ((float)mv.z - 2.0f) * 1.25e11f;
            o.w = ((float)mv.w - 2.0f) * 1.25e11f;
            stcs128(outrow0 + (size_t)r * SEQ + t0 + c4, o);
        }
        return;
    }

    __shared__ __align__(16) char sraw[36864];
    __nv_bfloat16 (*Qs)[72] = (__nv_bfloat16 (*)[72])sraw;
    __nv_bfloat16 (*Ks)[72] = (__nv_bfloat16 (*)[72])(sraw + 18432);
    float (*SF)[132] = (float (*)[132])sraw;

    const __nv_bfloat16* Qg = g_Q + ((size_t)bh * SEQ + s0) * DDIM;
    const __nv_bfloat16* Kg = g_K + ((size_t)bh * SEQ + t0) * DDIM;
    #pragma unroll
    for (int it = 0; it < 2; ++it) {
        int idx = tid + it * 512;
        int r = idx >> 3, c8 = (idx & 7) * 8;
        *(uint4*)&Qs[r][c8] = *(const uint4*)(Qg + (size_t)r * DDIM + c8);
        *(uint4*)&Ks[r][c8] = *(const uint4*)(Kg + (size_t)r * DDIM + c8);
    }
    __syncthreads();

    const int lane = tid & 31, wid = tid >> 5;
    const int warp_m = wid & 3, warp_n = wid >> 2;
    const int g = lane >> 2, t4 = lane & 3;

    float acc[2][4][4];
    #pragma unroll
    for (int mi = 0; mi < 2; ++mi)
        #pragma unroll
        for (int ni = 0; ni < 4; ++ni)
            #pragma unroll
            for (int q = 0; q < 4; ++q) acc[mi][ni][q] = 0.f;

    const uint32_t qbase = smem_u32(&Qs[0][0]);
    const uint32_t kbase = smem_u32(&Ks[0][0]);
    uint32_t arb[2], brb[2];
    #pragma unroll
    for (int mi = 0; mi < 2; ++mi) {
        int r = warp_m * 32 + mi * 16 + (lane & 15);
        arb[mi] = qbase + r * 144 + ((lane >> 4) << 4);
    }
    #pragma unroll
    for (int nj = 0; nj < 2; ++nj) {
        int n = warp_n * 32 + nj * 16 + ((lane >> 4) << 3) + (lane & 7);
        brb[nj] = kbase + n * 144 + (((lane >> 3) & 1) << 4);
    }

    #pragma unroll
    for (int kk = 0; kk < 64; kk += 16) {
        uint32_t a[2][4], b[2][4];
        #pragma unroll
        for (int mi = 0; mi < 2; ++mi)
            ldsm_x4(arb[mi] + kk * 2, a[mi]);
        #pragma unroll
        for (int nj = 0; nj < 2; ++nj)
            ldsm_x4(brb[nj] + kk * 2, b[nj]);
        #pragma unroll
        for (int mi = 0; mi < 2; ++mi)
            #pragma unroll
            for (int ni = 0; ni < 4; ++ni)
                mma16816(acc[mi][ni], a[mi], &b[ni >> 1][(ni & 1) * 2]);
    }

    __syncthreads();

    #pragma unroll
    for (int h = 0; h < 2; ++h) {
        if ((warp_m >> 1) == h) {
            const int rbase = (warp_m & 1) * 32;
            #pragma unroll
            for (int ni = 0; ni < 4; ++ni) {
                const int cl = warp_n * 32 + ni * 8 + t4 * 2;
                #pragma unroll
                for (int mi = 0; mi < 2; ++mi) {
                    #pragma unroll
                    for (int rr = 0; rr < 2; ++rr) {
                        const int rl = rbase + mi * 16 + g + rr * 8;
                        SF[rl][cl]     = acc[mi][ni][rr * 2 + 0];
                        SF[rl][cl + 1] = acc[mi][ni][rr * 2 + 1];
                    }
                }
            }
        }
        __syncthreads();
        #pragma unroll
        for (int it = 0; it < 4; ++it) {
            int idx = tid + it * 512;
            int r = idx >> 5, c16 = (idx & 31) * 4;
            int row = s0 + h * 64 + r;
            int4 mv = *(const int4*)(amask + bidx * SEQ + t0 + c16);
            float4 v = *(const float4*)&SF[r][c16];
            float p;
            p = (float)mv.x; v.x = (v.x * p - (1.f - p) * MASKV - ((t0 + c16     < row) ? MASKV : 0.f)) * 0.125f;
            p = (float)mv.y; v.y = (v.y * p - (1.f - p) * MASKV - ((t0 + c16 + 1 < row) ? MASKV : 0.f)) * 0.125f;
            p = (float)mv.z; v.z = (v.z * p - (1.f - p) * MASKV - ((t0 + c16 + 2 < row) ? MASKV : 0.f)) * 0.125f;
            p = (float)mv.w; v.w = (v.w * p - (1.f - p) * MASKV - ((t0 + c16 + 3 < row) ? MASKV : 0.f)) * 0.125f;
            stcs128(out + ((size_t)bh * SEQ + row) * SEQ + t0 + c16, v);
        }
        if (h == 0) __syncthreads();
    }
}

extern "C" void kernel_launch(void* const* d_in, const int* in_sizes, int n_in,
                              void* d_out, int out_size) {
    (void)in_sizes; (void)n_in; (void)out_size;
    const float* enc  = (const float*)d_in[0];
    const int*   am   = (const int*)d_in[2];
    const float* W    = (const float*)d_in[3];
    const float* bias = (const float*)d_in[4];
    float* out = (float*)d_out;

    __nv_bfloat16* encb; cudaGetSymbolAddress((void**)&encb, g_encb);
    __nv_bfloat16* Wt;   cudaGetSymbolAddress((void**)&Wt,   g_Wt);
    float2* rope;        cudaGetSymbolAddress((void**)&rope, g_rope);

    cudaFuncSetAttribute(gemm1_rope, cudaFuncAttributeMaxDynamicSharedMemorySize, G1_DYN);

    prep_enc<<<1536, 256>>>(enc, encb);
    prep_w<<<dim3(HID / 64, NQK / 64), 256>>>(W, Wt);
    prep_rope<<<(SEQ * 32 + 255) / 256, 256>>>(rope);

    dim3 g1(64, NUM_TAGS);
    gemm1_rope<<<g1, 128, G1_DYN>>>(bias);

    dim3 g2(4, 4, BATCH * NUM_TAGS);
    gemm2_mask<<<g2, 512>>>(am, out);
}

// round 9
// speedup vs baseline: 1.1117x; 1.1117x over previous
#include <cuda_runtime.h>
#include <cuda_fp16.h>
#include <cstdint>

#define NUM_TAGS 9
#define DDIM 64
#define HID 768
#define SEQ 512
#define BATCH 16
#define NQK (NUM_TAGS * 2 * DDIM)   /* 1152 */
#define MASKV 1e12f

// Scratch (fp16 everywhere)
__device__ __half g_Q[(size_t)BATCH * NUM_TAGS * SEQ * DDIM];
__device__ __half g_K[(size_t)BATCH * NUM_TAGS * SEQ * DDIM];
__device__ __half g_ench[(size_t)BATCH * SEQ * HID];
__device__ __half g_Wt[(size_t)NQK * HID];                       // W^T [n][k]
__device__ float2 g_rope[SEQ * 32];                              // (sin,cos) per (s,pair)

__device__ __forceinline__ uint32_t smem_u32(const void* p) {
    uint32_t a;
    asm("{ .reg .u64 t; cvta.to.shared.u64 t, %1; cvt.u32.u64 %0, t; }" : "=r"(a) : "l"(p));
    return a;
}
__device__ __forceinline__ void cpasync16s(uint32_t saddr, const void* g) {
    asm volatile("cp.async.cg.shared.global [%0], [%1], 16;\n" :: "r"(saddr), "l"(g));
}
#define CP_COMMIT() asm volatile("cp.async.commit_group;\n")
#define SW128(o) ((o) ^ (((o) >> 3) & 0x70))

// fp16 MMA, f16 accumulators (2 packed regs)
__device__ __forceinline__ void mma16816h(uint32_t* c, const uint32_t* a, const uint32_t* b) {
    asm volatile(
        "mma.sync.aligned.m16n8k16.row.col.f16.f16.f16.f16 "
        "{%0,%1}, {%2,%3,%4,%5}, {%6,%7}, {%0,%1};\n"
        : "+r"(c[0]), "+r"(c[1])
        : "r"(a[0]), "r"(a[1]), "r"(a[2]), "r"(a[3]), "r"(b[0]), "r"(b[1]));
}
__device__ __forceinline__ void ldsm_x4(uint32_t addr, uint32_t* r) {
    asm volatile("ldmatrix.sync.aligned.m8n8.x4.shared.b16 {%0,%1,%2,%3}, [%4];"
        : "=r"(r[0]), "=r"(r[1]), "=r"(r[2]), "=r"(r[3]) : "r"(addr));
}
__device__ __forceinline__ void stcs128(float* g, float4 v) {
    asm volatile("st.global.cs.v4.f32 [%0], {%1,%2,%3,%4};"
        :: "l"(g), "f"(v.x), "f"(v.y), "f"(v.z), "f"(v.w) : "memory");
}

// ===================== Prep kernels =====================
__global__ __launch_bounds__(256) void prep_enc(const float* __restrict__ enc,
                                                __half* __restrict__ dst) {
    const int NV = BATCH * SEQ * HID / 4;
    const int stride = gridDim.x * blockDim.x;
    for (int i = blockIdx.x * blockDim.x + threadIdx.x; i < NV; i += stride) {
        float4 v = *(const float4*)(enc + (size_t)i * 4);
        __half2 lo = __floats2half2_rn(v.x, v.y);
        __half2 hi = __floats2half2_rn(v.z, v.w);
        uint2 o = { *(unsigned*)&lo, *(unsigned*)&hi };
        *(uint2*)(dst + (size_t)i * 4) = o;
    }
}

__global__ __launch_bounds__(256) void prep_w(const float* __restrict__ W,
                                              __half* __restrict__ Wt) {
    __shared__ __half t[64][72];
    const int kb = blockIdx.x * 64, nb = blockIdx.y * 64;
    const int tid = threadIdx.x;
    #pragma unroll
    for (int it = 0; it < 4; ++it) {
        int idx = tid + it * 256;
        int r = idx >> 4, c4 = (idx & 15) * 4;
        float4 v = *(const float4*)(W + (size_t)(kb + r) * NQK + nb + c4);
        t[c4 + 0][r] = __float2half_rn(v.x);
        t[c4 + 1][r] = __float2half_rn(v.y);
        t[c4 + 2][r] = __float2half_rn(v.z);
        t[c4 + 3][r] = __float2half_rn(v.w);
    }
    __syncthreads();
    #pragma unroll
    for (int it = 0; it < 4; ++it) {
        int idx = tid + it * 256;
        int r = idx >> 4, c4 = (idx & 15) * 4;
        *(uint2*)(Wt + (size_t)(nb + r) * HID + kb + c4) = *(uint2*)&t[r][c4];
    }
}

__global__ __launch_bounds__(256) void prep_rope(float2* __restrict__ rope) {
    int i = blockIdx.x * blockDim.x + threadIdx.x;
    if (i >= SEQ * 32) return;
    int s = i >> 5, p = i & 31;
    const float LN1E4_OVER_32 = 0.28782313662425572f;
    float inv = expf(-(float)p * LN1E4_OVER_32);
    float sv, cv;
    sincosf((float)s * inv, &sv, &cv);
    rope[i] = make_float2(sv, cv);
}

// ===================== Kernel A: GEMM1 + bias + RoPE =====================
// CTA tile 128(M) x 128(N = one tag). 8 warps = 2(M) x 4(N); warp tile 64x32.
// K-tile 64 (SW128), 2-stage cp.async. fp16 in / f16 acc.
#define G1_KT 64
#define G1_NT (HID / G1_KT)          /* 12 */
#define G1_ASZ (128 * 128)           /* 16KB */
#define G1_STAGE (2 * G1_ASZ)        /* 32KB */
#define G1_DYN (2 * G1_STAGE + 256)

__global__ __launch_bounds__(256, 2) void gemm1_rope(const float* __restrict__ bias)
{
    extern __shared__ char dyn_raw[];
    const uint32_t dsm = (smem_u32(dyn_raw) + 127) & ~127u;
    __shared__ float s_bias[128];

    const int tid  = threadIdx.x;
    const int lane = tid & 31, wid = tid >> 5;
    const int warp_m = wid & 1;
    const int warp_n = wid >> 1;
    const int g  = lane >> 2;
    const int t4 = lane & 3;

    const int m0 = blockIdx.x * 128;
    const int tag = blockIdx.y;
    const int n0 = tag * 128;

    if (tid < 128) s_bias[tid] = bias[n0 + tid];

    const __half* Ag = g_ench + (size_t)m0 * HID;
    const __half* Bg = g_Wt   + (size_t)n0 * HID;

    uint32_t acc[4][4][2];
    #pragma unroll
    for (int mi = 0; mi < 4; ++mi)
        #pragma unroll
        for (int ni = 0; ni < 4; ++ni) { acc[mi][ni][0] = 0u; acc[mi][ni][1] = 0u; }

    auto load_tile = [&](int kt, int st) {
        const int k0 = kt * G1_KT;
        const uint32_t abase = dsm + st * G1_STAGE;
        const uint32_t bbase = abase + G1_ASZ;
        #pragma unroll
        for (int i = 0; i < 4; ++i) {
            int idx = tid + i * 256;
            int r = idx >> 3, c = idx & 7;
            uint32_t off = (uint32_t)(r * 128 + c * 16);
            cpasync16s(abase + SW128(off), Ag + (size_t)r * HID + k0 + c * 8);
        }
        #pragma unroll
        for (int i = 0; i < 4; ++i) {
            int idx = tid + i * 256;
            int r = idx >> 3, c = idx & 7;
            uint32_t off = (uint32_t)(r * 128 + c * 16);
            cpasync16s(bbase + SW128(off), Bg + (size_t)r * HID + k0 + c * 8);
        }
    };

    load_tile(0, 0); CP_COMMIT();
    load_tile(1, 1); CP_COMMIT();

    const uint32_t aK = ((lane >> 4) << 3) * 2;
    const uint32_t bK = (((lane >> 3) & 1) << 3) * 2;

    for (int kt = 0; kt < G1_NT; ++kt) {
        const int st = kt & 1;
        if (kt + 1 < G1_NT) asm volatile("cp.async.wait_group 1;\n" ::: "memory");
        else                asm volatile("cp.async.wait_group 0;\n" ::: "memory");
        __syncthreads();

        const uint32_t abase = dsm + st * G1_STAGE;
        const uint32_t bbase = abase + G1_ASZ;

        uint32_t arb[4], axv[4];
        #pragma unroll
        for (int mi = 0; mi < 4; ++mi) {
            int r = warp_m * 64 + mi * 16 + (lane & 15);
            arb[mi] = abase + r * 128;
            axv[mi] = (r & 7) << 4;
        }
        uint32_t brb[2], bxv[2];
        #pragma unroll
        for (int nj = 0; nj < 2; ++nj) {
            int n = warp_n * 32 + nj * 16 + ((lane >> 4) << 3) + (lane & 7);
            brb[nj] = bbase + n * 128;
            bxv[nj] = (n & 7) << 4;
        }

        #pragma unroll
        for (int kk2 = 0; kk2 < 128; kk2 += 32) {
            uint32_t a[4][4], b[2][4];
            #pragma unroll
            for (int mi = 0; mi < 4; ++mi)
                ldsm_x4(arb[mi] + ((kk2 + aK) ^ axv[mi]), a[mi]);
            #pragma unroll
            for (int nj = 0; nj < 2; ++nj)
                ldsm_x4(brb[nj] + ((kk2 + bK) ^ bxv[nj]), b[nj]);
            #pragma unroll
            for (int mi = 0; mi < 4; ++mi) {
                #pragma unroll
                for (int ni = 0; ni < 4; ++ni)
                    mma16816h(acc[mi][ni], a[mi], &b[ni >> 1][(ni & 1) * 2]);
            }
        }
        __syncthreads();
        if (kt + 2 < G1_NT) { load_tile(kt + 2, st); CP_COMMIT(); }
    }

    // ---- Epilogue: bias + RoPE -> fp16 Q/K ----
    #pragma unroll
    for (int ni = 0; ni < 4; ++ni) {
        const int col = warp_n * 32 + ni * 8 + t4 * 2;
        const bool isq = col < 64;
        const int dcol = col & 63;
        const float b0 = s_bias[col], b1 = s_bias[col + 1];
        __half* dstbase = isq ? g_Q : g_K;
        #pragma unroll
        for (int mi = 0; mi < 4; ++mi) {
            #pragma unroll
            for (int rr = 0; rr < 2; ++rr) {
                const int m = m0 + warp_m * 64 + mi * 16 + g + rr * 8;
                const int bb = m >> 9, s = m & 511;
                float2 sc = g_rope[s * 32 + (dcol >> 1)];
                __half2 hv = *(__half2*)&acc[mi][ni][rr];
                float v0 = __low2float(hv) + b0;
                float v1 = __high2float(hv) + b1;
                float y0 = v0 * sc.y - v1 * sc.x;
                float y1 = v1 * sc.y + v0 * sc.x;
                size_t off = (((size_t)(bb * NUM_TAGS + tag) * SEQ + s) * DDIM + dcol);
                *(__half2*)(dstbase + off) = __floats2half2_rn(y0, y1);
            }
        }
    }
}

// ===================== Kernel B: QK^T + mask + scale =====================
// 512 threads, 16 warps as 4(m)x4(n), warp tile 32x32, ldmatrix, f16 acc.
// Epilogue staged through smem -> coalesced float4 streaming stores.
__global__ __launch_bounds__(512, 2) void gemm2_mask(
    const int* __restrict__ amask, float* __restrict__ out)
{
    const int tt = blockIdx.x;
    const int st = blockIdx.y;
    const int bh = blockIdx.z;
    const int bidx = bh / NUM_TAGS;
    const int t0 = tt * 128, s0 = st * 128;
    const int tid = threadIdx.x;

    float* outrow0 = out + ((size_t)bh * SEQ + s0) * SEQ;

    if (t0 < s0) {
        #pragma unroll
        for (int it = 0; it < 8; ++it) {
            int idx = tid + it * 512;
            int r = idx >> 5, c4 = (idx & 31) * 4;
            int4 mv = *(const int4*)(amask + bidx * SEQ + t0 + c4);
            float4 o;
            o.x = ((float)mv.x - 2.0f) * 1.25e11f;
            o.y = ((float)mv.y - 2.0f) * 1.25e11f;
            o.z = ((float)mv.z - 2.0f) * 1.25e11f;
            o.w = ((float)mv.w - 2.0f) * 1.25e11f;
            stcs128(outrow0 + (size_t)r * SEQ + t0 + c4, o);
        }
        return;
    }

    __shared__ __align__(16) char sraw[36864];
    __half (*Qs)[72] = (__half (*)[72])sraw;
    __half (*Ks)[72] = (__half (*)[72])(sraw + 18432);
    float (*SF)[132] = (float (*)[132])sraw;

    const __half* Qg = g_Q + ((size_t)bh * SEQ + s0) * DDIM;
    const __half* Kg = g_K + ((size_t)bh * SEQ + t0) * DDIM;
    #pragma unroll
    for (int it = 0; it < 2; ++it) {
        int idx = tid + it * 512;
        int r = idx >> 3, c8 = (idx & 7) * 8;
        *(uint4*)&Qs[r][c8] = *(const uint4*)(Qg + (size_t)r * DDIM + c8);
        *(uint4*)&Ks[r][c8] = *(const uint4*)(Kg + (size_t)r * DDIM + c8);
    }
    __syncthreads();

    const int lane = tid & 31, wid = tid >> 5;
    const int warp_m = wid & 3, warp_n = wid >> 2;
    const int g = lane >> 2, t4 = lane & 3;

    uint32_t acc[2][4][2];
    #pragma unroll
    for (int mi = 0; mi < 2; ++mi)
        #pragma unroll
        for (int ni = 0; ni < 4; ++ni) { acc[mi][ni][0] = 0u; acc[mi][ni][1] = 0u; }

    const uint32_t qbase = smem_u32(&Qs[0][0]);
    const uint32_t kbase = smem_u32(&Ks[0][0]);
    uint32_t arb[2], brb[2];
    #pragma unroll
    for (int mi = 0; mi < 2; ++mi) {
        int r = warp_m * 32 + mi * 16 + (lane & 15);
        arb[mi] = qbase + r * 144 + ((lane >> 4) << 4);
    }
    #pragma unroll
    for (int nj = 0; nj < 2; ++nj) {
        int n = warp_n * 32 + nj * 16 + ((lane >> 4) << 3) + (lane & 7);
        brb[nj] = kbase + n * 144 + (((lane >> 3) & 1) << 4);
    }

    #pragma unroll
    for (int kk = 0; kk < 64; kk += 16) {
        uint32_t a[2][4], b[2][4];
        #pragma unroll
        for (int mi = 0; mi < 2; ++mi)
            ldsm_x4(arb[mi] + kk * 2, a[mi]);
        #pragma unroll
        for (int nj = 0; nj < 2; ++nj)
            ldsm_x4(brb[nj] + kk * 2, b[nj]);
        #pragma unroll
        for (int mi = 0; mi < 2; ++mi)
            #pragma unroll
            for (int ni = 0; ni < 4; ++ni)
                mma16816h(acc[mi][ni], a[mi], &b[ni >> 1][(ni & 1) * 2]);
    }

    __syncthreads();

    #pragma unroll
    for (int h = 0; h < 2; ++h) {
        if ((warp_m >> 1) == h) {
            const int rbase = (warp_m & 1) * 32;
            #pragma unroll
            for (int ni = 0; ni < 4; ++ni) {
                const int cl = warp_n * 32 + ni * 8 + t4 * 2;
                #pragma unroll
                for (int mi = 0; mi < 2; ++mi) {
                    #pragma unroll
                    for (int rr = 0; rr < 2; ++rr) {
                        const int rl = rbase + mi * 16 + g + rr * 8;
                        __half2 hv = *(__half2*)&acc[mi][ni][rr];
                        SF[rl][cl]     = __low2float(hv);
                        SF[rl][cl + 1] = __high2float(hv);
                    }
                }
            }
        }
        __syncthreads();
        #pragma unroll
        for (int it = 0; it < 4; ++it) {
            int idx = tid + it * 512;
            int r = idx >> 5, c16 = (idx & 31) * 4;
            int row = s0 + h * 64 + r;
            int4 mv = *(const int4*)(amask + bidx * SEQ + t0 + c16);
            float4 v = *(const float4*)&SF[r][c16];
            float p;
            p = (float)mv.x; v.x = (v.x * p - (1.f - p) * MASKV - ((t0 + c16     < row) ? MASKV : 0.f)) * 0.125f;
            p = (float)mv.y; v.y = (v.y * p - (1.f - p) * MASKV - ((t0 + c16 + 1 < row) ? MASKV : 0.f)) * 0.125f;
            p = (float)mv.z; v.z = (v.z * p - (1.f - p) * MASKV - ((t0 + c16 + 2 < row) ? MASKV : 0.f)) * 0.125f;
            p = (float)mv.w; v.w = (v.w * p - (1.f - p) * MASKV - ((t0 + c16 + 3 < row) ? MASKV : 0.f)) * 0.125f;
            stcs128(out + ((size_t)bh * SEQ + row) * SEQ + t0 + c16, v);
        }
        if (h == 0) __syncthreads();
    }
}

extern "C" void kernel_launch(void* const* d_in, const int* in_sizes, int n_in,
                              void* d_out, int out_size) {
    (void)in_sizes; (void)n_in; (void)out_size;
    const float* enc  = (const float*)d_in[0];
    const int*   am   = (const int*)d_in[2];
    const float* W    = (const float*)d_in[3];
    const float* bias = (const float*)d_in[4];
    float* out = (float*)d_out;

    __half* ench; cudaGetSymbolAddress((void**)&ench, g_ench);
    __half* Wt;   cudaGetSymbolAddress((void**)&Wt,   g_Wt);
    float2* rope; cudaGetSymbolAddress((void**)&rope, g_rope);

    cudaFuncSetAttribute(gemm1_rope, cudaFuncAttributeMaxDynamicSharedMemorySize, G1_DYN);

    prep_enc<<<1536, 256>>>(enc, ench);
    prep_w<<<dim3(HID / 64, NQK / 64), 256>>>(W, Wt);
    prep_rope<<<(SEQ * 32 + 255) / 256, 256>>>(rope);

    dim3 g1(64, NUM_TAGS);
    gemm1_rope<<<g1, 256, G1_DYN>>>(bias);

    dim3 g2(4, 4, BATCH * NUM_TAGS);
    gemm2_mask<<<g2, 512>>>(am, out);
}

// round 10
// speedup vs baseline: 1.1420x; 1.0273x over previous
#include <cuda_runtime.h>
#include <cuda_fp16.h>
#include <cstdint>

#define NUM_TAGS 9
#define DDIM 64
#define HID 768
#define SEQ 512
#define BATCH 16
#define NQK (NUM_TAGS * 2 * DDIM)   /* 1152 */
#define MASKV 1e12f

// Scratch (fp16 everywhere)
__device__ __half g_Q[(size_t)BATCH * NUM_TAGS * SEQ * DDIM];
__device__ __half g_K[(size_t)BATCH * NUM_TAGS * SEQ * DDIM];
__device__ __half g_ench[(size_t)BATCH * SEQ * HID];
__device__ __half g_Wt[(size_t)NQK * HID];                       // W^T [n][k]
__device__ float2 g_rope[SEQ * 32];                              // (sin,cos) per (s,pair)

__device__ __forceinline__ uint32_t smem_u32(const void* p) {
    uint32_t a;
    asm("{ .reg .u64 t; cvta.to.shared.u64 t, %1; cvt.u32.u64 %0, t; }" : "=r"(a) : "l"(p));
    return a;
}
__device__ __forceinline__ void cpasync16s(uint32_t saddr, const void* g) {
    asm volatile("cp.async.cg.shared.global [%0], [%1], 16;\n" :: "r"(saddr), "l"(g));
}
#define CP_COMMIT() asm volatile("cp.async.commit_group;\n")
#define SW128(o) ((o) ^ (((o) >> 3) & 0x70))

// fp16 MMA, f16 accumulators (2 packed regs)
__device__ __forceinline__ void mma16816h(uint32_t* c, const uint32_t* a, const uint32_t* b) {
    asm volatile(
        "mma.sync.aligned.m16n8k16.row.col.f16.f16.f16.f16 "
        "{%0,%1}, {%2,%3,%4,%5}, {%6,%7}, {%0,%1};\n"
        : "+r"(c[0]), "+r"(c[1])
        : "r"(a[0]), "r"(a[1]), "r"(a[2]), "r"(a[3]), "r"(b[0]), "r"(b[1]));
}
__device__ __forceinline__ void ldsm_x4(uint32_t addr, uint32_t* r) {
    asm volatile("ldmatrix.sync.aligned.m8n8.x4.shared.b16 {%0,%1,%2,%3}, [%4];"
        : "=r"(r[0]), "=r"(r[1]), "=r"(r[2]), "=r"(r[3]) : "r"(addr));
}
__device__ __forceinline__ void stcs128(float* g, float4 v) {
    asm volatile("st.global.cs.v4.f32 [%0], {%1,%2,%3,%4};"
        :: "l"(g), "f"(v.x), "f"(v.y), "f"(v.z), "f"(v.w) : "memory");
}

// ===================== Merged prep kernel =====================
// blocks [0,1536): enc fp32->fp16 ; [1536,1752): W transpose tiles ; [1752,1816): rope
__global__ __launch_bounds__(256) void prep_all(
    const float* __restrict__ enc, __half* __restrict__ ench,
    const float* __restrict__ W, __half* __restrict__ Wt,
    float2* __restrict__ rope)
{
    __shared__ __half t[64][72];
    const int b = blockIdx.x;
    const int tid = threadIdx.x;

    if (b < 1536) {
        const int NV = BATCH * SEQ * HID / 4;
        for (int i = b * 256 + tid; i < NV; i += 1536 * 256) {
            float4 v = *(const float4*)(enc + (size_t)i * 4);
            __half2 lo = __floats2half2_rn(v.x, v.y);
            __half2 hi = __floats2half2_rn(v.z, v.w);
            uint2 o = { *(unsigned*)&lo, *(unsigned*)&hi };
            *(uint2*)(ench + (size_t)i * 4) = o;
        }
    } else if (b < 1536 + 216) {
        const int w = b - 1536;
        const int kb = (w % 12) * 64, nb = (w / 12) * 64;
        #pragma unroll
        for (int it = 0; it < 4; ++it) {
            int idx = tid + it * 256;
            int r = idx >> 4, c4 = (idx & 15) * 4;
            float4 v = *(const float4*)(W + (size_t)(kb + r) * NQK + nb + c4);
            t[c4 + 0][r] = __float2half_rn(v.x);
            t[c4 + 1][r] = __float2half_rn(v.y);
            t[c4 + 2][r] = __float2half_rn(v.z);
            t[c4 + 3][r] = __float2half_rn(v.w);
        }
        __syncthreads();
        #pragma unroll
        for (int it = 0; it < 4; ++it) {
            int idx = tid + it * 256;
            int r = idx >> 4, c4 = (idx & 15) * 4;
            *(uint2*)(Wt + (size_t)(nb + r) * HID + kb + c4) = *(uint2*)&t[r][c4];
        }
    } else {
        int i = (b - 1752) * 256 + tid;
        if (i < SEQ * 32) {
            int s = i >> 5, p = i & 31;
            const float LN1E4_OVER_32 = 0.28782313662425572f;
            float inv = expf(-(float)p * LN1E4_OVER_32);
            float sv, cv;
            sincosf((float)s * inv, &sv, &cv);
            rope[i] = make_float2(sv, cv);
        }
    }
}

// ===================== Kernel A: GEMM1 + bias + RoPE + masked-tile fill ======
// CTA tile 128(M) x 128(N = one tag). 8 warps = 2(M) x 4(N); warp tile 64x32.
// K-tile 64 (SW128), 2-stage cp.async, fp16 in / f16 acc.
// Prologue additionally streams the causal-masked output tiles (DRAM idle here).
#define G1_KT 64
#define G1_NT (HID / G1_KT)          /* 12 */
#define G1_ASZ (128 * 128)           /* 16KB */
#define G1_STAGE (2 * G1_ASZ)        /* 32KB */
#define G1_DYN (2 * G1_STAGE + 256)

__global__ __launch_bounds__(256, 2) void gemm1_rope(
    const float* __restrict__ bias, const int* __restrict__ amask,
    float* __restrict__ out)
{
    extern __shared__ char dyn_raw[];
    const uint32_t dsm = (smem_u32(dyn_raw) + 127) & ~127u;
    __shared__ float s_bias[128];

    const int tid  = threadIdx.x;
    const int lane = tid & 31, wid = tid >> 5;
    const int warp_m = wid & 1;
    const int warp_n = wid >> 1;
    const int g  = lane >> 2;
    const int t4 = lane & 3;

    const int m0 = blockIdx.x * 128;
    const int tag = blockIdx.y;
    const int n0 = tag * 128;

    if (tid < 128) s_bias[tid] = bias[n0 + tid];

    const __half* Ag = g_ench + (size_t)m0 * HID;
    const __half* Bg = g_Wt   + (size_t)n0 * HID;

    uint32_t acc[4][4][2];
    #pragma unroll
    for (int mi = 0; mi < 4; ++mi)
        #pragma unroll
        for (int ni = 0; ni < 4; ++ni) { acc[mi][ni][0] = 0u; acc[mi][ni][1] = 0u; }

    auto load_tile = [&](int kt, int st) {
        const int k0 = kt * G1_KT;
        const uint32_t abase = dsm + st * G1_STAGE;
        const uint32_t bbase = abase + G1_ASZ;
        #pragma unroll
        for (int i = 0; i < 4; ++i) {
            int idx = tid + i * 256;
            int r = idx >> 3, c = idx & 7;
            uint32_t off = (uint32_t)(r * 128 + c * 16);
            cpasync16s(abase + SW128(off), Ag + (size_t)r * HID + k0 + c * 8);
        }
        #pragma unroll
        for (int i = 0; i < 4; ++i) {
            int idx = tid + i * 256;
            int r = idx >> 3, c = idx & 7;
            uint32_t off = (uint32_t)(r * 128 + c * 16);
            cpasync16s(bbase + SW128(off), Bg + (size_t)r * HID + k0 + c * 8);
        }
    };

    load_tile(0, 0); CP_COMMIT();
    load_tile(1, 1); CP_COMMIT();

    // ---- Causal-masked output tile fill (independent of GEMM; DRAM idle) ----
    // 144 bh x 6 tiles x 128 rows x 32 float4 = 3,538,944 float4 over 576 CTAs.
    {
        const int cid = tag * 64 + blockIdx.x;            // 0..575
        const int ST[6] = {1, 2, 2, 3, 3, 3};
        const int TT[6] = {0, 0, 1, 0, 1, 2};
        #pragma unroll 4
        for (int k_ = 0; k_ < 24; ++k_) {
            int idx = cid * 6144 + k_ * 256 + tid;
            int tile_id = idx >> 12;                      // /4096
            int within = idx & 4095;
            int row = within >> 5, c4 = (within & 31) << 2;
            int bh = tile_id / 6, mt = tile_id - bh * 6;
            int bidx = bh / NUM_TAGS;
            int s0 = ST[mt] * 128, t0 = TT[mt] * 128;
            int4 mv = *(const int4*)(amask + bidx * SEQ + t0 + c4);
            float4 o;
            o.x = ((float)mv.x - 2.0f) * 1.25e11f;
            o.y = ((float)mv.y - 2.0f) * 1.25e11f;
            o.z = ((float)mv.z - 2.0f) * 1.25e11f;
            o.w = ((float)mv.w - 2.0f) * 1.25e11f;
            stcs128(out + ((size_t)bh * SEQ + s0 + row) * SEQ + t0 + c4, o);
        }
    }

    const uint32_t aK = ((lane >> 4) << 3) * 2;
    const uint32_t bK = (((lane >> 3) & 1) << 3) * 2;

    for (int kt = 0; kt < G1_NT; ++kt) {
        const int st = kt & 1;
        if (kt + 1 < G1_NT) asm volatile("cp.async.wait_group 1;\n" ::: "memory");
        else                asm volatile("cp.async.wait_group 0;\n" ::: "memory");
        __syncthreads();

        const uint32_t abase = dsm + st * G1_STAGE;
        const uint32_t bbase = abase + G1_ASZ;

        uint32_t arb[4], axv[4];
        #pragma unroll
        for (int mi = 0; mi < 4; ++mi) {
            int r = warp_m * 64 + mi * 16 + (lane & 15);
            arb[mi] = abase + r * 128;
            axv[mi] = (r & 7) << 4;
        }
        uint32_t brb[2], bxv[2];
        #pragma unroll
        for (int nj = 0; nj < 2; ++nj) {
            int n = warp_n * 32 + nj * 16 + ((lane >> 4) << 3) + (lane & 7);
            brb[nj] = bbase + n * 128;
            bxv[nj] = (n & 7) << 4;
        }

        #pragma unroll
        for (int kk2 = 0; kk2 < 128; kk2 += 32) {
            uint32_t a[4][4], b[2][4];
            #pragma unroll
            for (int mi = 0; mi < 4; ++mi)
                ldsm_x4(arb[mi] + ((kk2 + aK) ^ axv[mi]), a[mi]);
            #pragma unroll
            for (int nj = 0; nj < 2; ++nj)
                ldsm_x4(brb[nj] + ((kk2 + bK) ^ bxv[nj]), b[nj]);
            #pragma unroll
            for (int mi = 0; mi < 4; ++mi) {
                #pragma unroll
                for (int ni = 0; ni < 4; ++ni)
                    mma16816h(acc[mi][ni], a[mi], &b[ni >> 1][(ni & 1) * 2]);
            }
        }
        __syncthreads();
        if (kt + 2 < G1_NT) { load_tile(kt + 2, st); CP_COMMIT(); }
    }

    // ---- Epilogue: bias + RoPE -> fp16 Q/K ----
    #pragma unroll
    for (int ni = 0; ni < 4; ++ni) {
        const int col = warp_n * 32 + ni * 8 + t4 * 2;
        const bool isq = col < 64;
        const int dcol = col & 63;
        const float b0 = s_bias[col], b1 = s_bias[col + 1];
        __half* dstbase = isq ? g_Q : g_K;
        #pragma unroll
        for (int mi = 0; mi < 4; ++mi) {
            #pragma unroll
            for (int rr = 0; rr < 2; ++rr) {
                const int m = m0 + warp_m * 64 + mi * 16 + g + rr * 8;
                const int bb = m >> 9, s = m & 511;
                float2 sc = g_rope[s * 32 + (dcol >> 1)];
                __half2 hv = *(__half2*)&acc[mi][ni][rr];
                float v0 = __low2float(hv) + b0;
                float v1 = __high2float(hv) + b1;
                float y0 = v0 * sc.y - v1 * sc.x;
                float y1 = v1 * sc.y + v0 * sc.x;
                size_t off = (((size_t)(bb * NUM_TAGS + tag) * SEQ + s) * DDIM + dcol);
                *(__half2*)(dstbase + off) = __floats2half2_rn(y0, y1);
            }
        }
    }
}

// ===================== Kernel B: QK^T + mask + scale (upper tiles only) ======
// grid (10, 144): only tiles with t0 >= s0. 512 threads, 16 warps 4x4,
// warp tile 32x32, ldmatrix, f16 acc, smem-staged coalesced epilogue.
__global__ __launch_bounds__(512, 2) void gemm2_mask(
    const int* __restrict__ amask, float* __restrict__ out)
{
    const int ST2[10] = {0, 1, 2, 3, 0, 0, 0, 1, 1, 2};
    const int TT2[10] = {0, 1, 2, 3, 1, 2, 3, 2, 3, 3};
    const int st = ST2[blockIdx.x], tt = TT2[blockIdx.x];
    const int bh = blockIdx.y;
    const int bidx = bh / NUM_TAGS;
    const int t0 = tt * 128, s0 = st * 128;
    const int tid = threadIdx.x;

    __shared__ __align__(16) char sraw[36864];
    __half (*Qs)[72] = (__half (*)[72])sraw;
    __half (*Ks)[72] = (__half (*)[72])(sraw + 18432);
    float (*SF)[132] = (float (*)[132])sraw;

    const __half* Qg = g_Q + ((size_t)bh * SEQ + s0) * DDIM;
    const __half* Kg = g_K + ((size_t)bh * SEQ + t0) * DDIM;
    #pragma unroll
    for (int it = 0; it < 2; ++it) {
        int idx = tid + it * 512;
        int r = idx >> 3, c8 = (idx & 7) * 8;
        *(uint4*)&Qs[r][c8] = *(const uint4*)(Qg + (size_t)r * DDIM + c8);
        *(uint4*)&Ks[r][c8] = *(const uint4*)(Kg + (size_t)r * DDIM + c8);
    }
    __syncthreads();

    const int lane = tid & 31, wid = tid >> 5;
    const int warp_m = wid & 3, warp_n = wid >> 2;
    const int g = lane >> 2, t4 = lane & 3;

    uint32_t acc[2][4][2];
    #pragma unroll
    for (int mi = 0; mi < 2; ++mi)
        #pragma unroll
        for (int ni = 0; ni < 4; ++ni) { acc[mi][ni][0] = 0u; acc[mi][ni][1] = 0u; }

    const uint32_t qbase = smem_u32(&Qs[0][0]);
    const uint32_t kbase = smem_u32(&Ks[0][0]);
    uint32_t arb[2], brb[2];
    #pragma unroll
    for (int mi = 0; mi < 2; ++mi) {
        int r = warp_m * 32 + mi * 16 + (lane & 15);
        arb[mi] = qbase + r * 144 + ((lane >> 4) << 4);
    }
    #pragma unroll
    for (int nj = 0; nj < 2; ++nj) {
        int n = warp_n * 32 + nj * 16 + ((lane >> 4) << 3) + (lane & 7);
        brb[nj] = kbase + n * 144 + (((lane >> 3) & 1) << 4);
    }

    #pragma unroll
    for (int kk = 0; kk < 64; kk += 16) {
        uint32_t a[2][4], b[2][4];
        #pragma unroll
        for (int mi = 0; mi < 2; ++mi)
            ldsm_x4(arb[mi] + kk * 2, a[mi]);
        #pragma unroll
        for (int nj = 0; nj < 2; ++nj)
            ldsm_x4(brb[nj] + kk * 2, b[nj]);
        #pragma unroll
        for (int mi = 0; mi < 2; ++mi)
            #pragma unroll
            for (int ni = 0; ni < 4; ++ni)
                mma16816h(acc[mi][ni], a[mi], &b[ni >> 1][(ni & 1) * 2]);
    }

    __syncthreads();

    #pragma unroll
    for (int h = 0; h < 2; ++h) {
        if ((warp_m >> 1) == h) {
            const int rbase = (warp_m & 1) * 32;
            #pragma unroll
            for (int ni = 0; ni < 4; ++ni) {
                const int cl = warp_n * 32 + ni * 8 + t4 * 2;
                #pragma unroll
                for (int mi = 0; mi < 2; ++mi) {
                    #pragma unroll
                    for (int rr = 0; rr < 2; ++rr) {
                        const int rl = rbase + mi * 16 + g + rr * 8;
                        __half2 hv = *(__half2*)&acc[mi][ni][rr];
                        SF[rl][cl]     = __low2float(hv);
                        SF[rl][cl + 1] = __high2float(hv);
                    }
                }
            }
        }
        __syncthreads();
        #pragma unroll
        for (int it = 0; it < 4; ++it) {
            int idx = tid + it * 512;
            int r = idx >> 5, c16 = (idx & 31) * 4;
            int row = s0 + h * 64 + r;
            int4 mv = *(const int4*)(amask + bidx * SEQ + t0 + c16);
            float4 v = *(const float4*)&SF[r][c16];
            float p;
            p = (float)mv.x; v.x = (v.x * p - (1.f - p) * MASKV - ((t0 + c16     < row) ? MASKV : 0.f)) * 0.125f;
            p = (float)mv.y; v.y = (v.y * p - (1.f - p) * MASKV - ((t0 + c16 + 1 < row) ? MASKV : 0.f)) * 0.125f;
            p = (float)mv.z; v.z = (v.z * p - (1.f - p) * MASKV - ((t0 + c16 + 2 < row) ? MASKV : 0.f)) * 0.125f;
            p = (float)mv.w; v.w = (v.w * p - (1.f - p) * MASKV - ((t0 + c16 + 3 < row) ? MASKV : 0.f)) * 0.125f;
            stcs128(out + ((size_t)bh * SEQ + row) * SEQ + t0 + c16, v);
        }
        if (h == 0) __syncthreads();
    }
}

extern "C" void kernel_launch(void* const* d_in, const int* in_sizes, int n_in,
                              void* d_out, int out_size) {
    (void)in_sizes; (void)n_in; (void)out_size;
    const float* enc  = (const float*)d_in[0];
    const int*   am   = (const int*)d_in[2];
    const float* W    = (const float*)d_in[3];
    const float* bias = (const float*)d_in[4];
    float* out = (float*)d_out;

    __half* ench; cudaGetSymbolAddress((void**)&ench, g_ench);
    __half* Wt;   cudaGetSymbolAddress((void**)&Wt,   g_Wt);
    float2* rope; cudaGetSymbolAddress((void**)&rope, g_rope);

    cudaFuncSetAttribute(gemm1_rope, cudaFuncAttributeMaxDynamicSharedMemorySize, G1_DYN);

    prep_all<<<1816, 256>>>(enc, ench, W, Wt, rope);

    dim3 g1(64, NUM_TAGS);
    gemm1_rope<<<g1, 256, G1_DYN>>>(bias, am, out);

    dim3 g2(10, BATCH * NUM_TAGS);
    gemm2_mask<<<g2, 512>>>(am, out);
}